// round 1
// baseline (speedup 1.0000x reference)
#include <cuda_runtime.h>

#define D_DIM 768
#define VEC   (D_DIM / 4)     // 192 float4 per row
#define NTHR  192             // one float4 per thread
#define NWARP (NTHR / 32)     // 6 warps
#define LN_EPS 1e-6f

__global__ __launch_bounds__(NTHR)
void hier_attn_ln_kernel(const int*   __restrict__ ids,
                         const float* __restrict__ pooler,
                         const float* __restrict__ emb,     // (V,2)
                         const float* __restrict__ Wd,      // (2,D)
                         const float* __restrict__ bd,      // (D)
                         const float* __restrict__ gamma,   // (D)
                         const float* __restrict__ beta,    // (D)
                         float*       __restrict__ out,
                         int L)
{
    const int bl = blockIdx.x;            // row index in [0, B*L)
    const int b  = bl / L;
    const int t  = threadIdx.x;

    // ---- load p (one float4 per thread, stays in registers) ----
    const float4* prow = reinterpret_cast<const float4*>(pooler + (size_t)bl * D_DIM);
    float4 p = prow[t];

    // ---- compute x_d = e0*W0[d] + e1*W1[d] + b[d] on the fly ----
    const int   id = __ldg(ids + b);
    const float e0 = __ldg(emb + 2 * id);
    const float e1 = __ldg(emb + 2 * id + 1);
    float4 w0 = reinterpret_cast<const float4*>(Wd)[t];
    float4 w1 = reinterpret_cast<const float4*>(Wd + D_DIM)[t];
    float4 bb = reinterpret_cast<const float4*>(bd)[t];
    float4 x;
    x.x = fmaf(e0, w0.x, fmaf(e1, w1.x, bb.x));
    x.y = fmaf(e0, w0.y, fmaf(e1, w1.y, bb.y));
    x.z = fmaf(e0, w0.z, fmaf(e1, w1.z, bb.z));
    x.w = fmaf(e0, w0.w, fmaf(e1, w1.w, bb.w));

    // ---- per-thread partials: pp, px, Sp, xx, Sx ----
    float pp = p.x*p.x + p.y*p.y + p.z*p.z + p.w*p.w;
    float px = p.x*x.x + p.y*x.y + p.z*x.z + p.w*x.w;
    float Sp = p.x + p.y + p.z + p.w;
    float xx = x.x*x.x + x.y*x.y + x.z*x.z + x.w*x.w;
    float Sx = x.x + x.y + x.z + x.w;

    // ---- block reduce (warp shuffle, then smem across 6 warps) ----
    #pragma unroll
    for (int off = 16; off > 0; off >>= 1) {
        pp += __shfl_down_sync(0xffffffffu, pp, off);
        px += __shfl_down_sync(0xffffffffu, px, off);
        Sp += __shfl_down_sync(0xffffffffu, Sp, off);
        xx += __shfl_down_sync(0xffffffffu, xx, off);
        Sx += __shfl_down_sync(0xffffffffu, Sx, off);
    }
    __shared__ float red[5][NWARP];
    const int warp = t >> 5, lane = t & 31;
    if (lane == 0) {
        red[0][warp] = pp; red[1][warp] = px; red[2][warp] = Sp;
        red[3][warp] = xx; red[4][warp] = Sx;
    }
    __syncthreads();
    pp = red[0][0]; px = red[1][0]; Sp = red[2][0]; xx = red[3][0]; Sx = red[4][0];
    #pragma unroll
    for (int w = 1; w < NWARP; ++w) {
        pp += red[0][w]; px += red[1][w]; Sp += red[2][w];
        xx += red[3][w]; Sx += red[4][w];
    }

    // ---- 2x2 safe softmax, rows [pp,px] and [px,xx] ----
    float m0  = fmaxf(pp, px);
    float e00 = __expf(pp - m0), e01 = __expf(px - m0);
    float d0  = e00 + e01;
    float a00 = e00 / d0,        a01 = e01 / d0;

    float m1  = fmaxf(px, xx);
    float e10 = __expf(px - m1), e11 = __expf(xx - m1);
    float d1  = e10 + e11;
    float a10 = e10 / d1,        a11 = e11 / d1;

    float wp = a00 + a10;                 // weight on p
    float wx = a01 + a11;                 // weight on x

    // ---- analytic layernorm stats of summed = wp*p + wx*x ----
    const float invD = 1.0f / (float)D_DIM;
    float mean = (wp * Sp + wx * Sx) * invD;
    float ss2  = wp*wp*pp + 2.0f*wp*wx*px + wx*wx*xx;   // sum of squares
    float var  = ss2 * invD - mean * mean;
    float inv  = rsqrtf(var + LN_EPS);

    // ---- write output ----
    float4 g = reinterpret_cast<const float4*>(gamma)[t];
    float4 be = reinterpret_cast<const float4*>(beta)[t];
    float4 o;
    o.x = (wp * p.x + wx * x.x - mean) * inv * g.x + be.x;
    o.y = (wp * p.y + wx * x.y - mean) * inv * g.y + be.y;
    o.z = (wp * p.z + wx * x.z - mean) * inv * g.z + be.z;
    o.w = (wp * p.w + wx * x.w - mean) * inv * g.w + be.w;
    reinterpret_cast<float4*>(out + (size_t)bl * D_DIM)[t] = o;
}

extern "C" void kernel_launch(void* const* d_in, const int* in_sizes, int n_in,
                              void* d_out, int out_size)
{
    const int*   ids    = (const int*)  d_in[0];
    const float* pooler = (const float*)d_in[1];
    const float* emb    = (const float*)d_in[2];
    const float* Wd     = (const float*)d_in[3];
    const float* bd     = (const float*)d_in[4];
    const float* gamma  = (const float*)d_in[5];
    const float* beta   = (const float*)d_in[6];
    float* out = (float*)d_out;

    const int B = in_sizes[0];                      // ids is (B,1)
    const int L = in_sizes[1] / (B * D_DIM);        // pooler is (B,L,D)

    hier_attn_ln_kernel<<<B * L, NTHR>>>(ids, pooler, emb, Wd, bd, gamma, beta, out, L);
}

// round 2
// speedup vs baseline: 1.8103x; 1.8103x over previous
#include <cuda_runtime.h>

#define D_DIM   768
#define F4_ROW  (D_DIM / 4)        // 192 float4 per row
#define F4_LANE 6                  // float4 per lane (192/32)
#define WARPS   8
#define NTHR    (WARPS * 32)
#define RPW     8                  // rows per warp
#define LN_EPS  1e-6f

__global__ __launch_bounds__(NTHR)
void hier_attn_ln_kernel(const int*   __restrict__ ids,
                         const float* __restrict__ pooler,
                         const float* __restrict__ emb,     // (V,2)
                         const float* __restrict__ Wd,      // (2,D)
                         const float* __restrict__ bd,      // (D)
                         const float* __restrict__ gamma,   // (D)
                         const float* __restrict__ beta,    // (D)
                         float*       __restrict__ out,
                         int L)
{
    const int b    = blockIdx.y;
    const int warp = threadIdx.x >> 5;
    const int lane = threadIdx.x & 31;
    const int l0   = (blockIdx.x * WARPS + warp) * RPW;
    if (l0 >= L) return;

    const float4* W0 = reinterpret_cast<const float4*>(Wd);
    const float4* W1 = reinterpret_cast<const float4*>(Wd + D_DIM);
    const float4* BB = reinterpret_cast<const float4*>(bd);
    const float4* GG = reinterpret_cast<const float4*>(gamma);
    const float4* BE = reinterpret_cast<const float4*>(beta);

    // ---- per-batch constants, loaded/computed ONCE per warp ----
    const int   id = __ldg(ids + b);
    const float e0 = __ldg(emb + 2 * id);
    const float e1 = __ldg(emb + 2 * id + 1);

    float4 x[F4_LANE], g[F4_LANE], be[F4_LANE];
    float Sx = 0.f, xx = 0.f;
    #pragma unroll
    for (int j = 0; j < F4_LANE; ++j) {
        const int c = lane + 32 * j;
        float4 w0 = W0[c], w1 = W1[c], bb = BB[c];
        float4 xv;
        xv.x = fmaf(e0, w0.x, fmaf(e1, w1.x, bb.x));
        xv.y = fmaf(e0, w0.y, fmaf(e1, w1.y, bb.y));
        xv.z = fmaf(e0, w0.z, fmaf(e1, w1.z, bb.z));
        xv.w = fmaf(e0, w0.w, fmaf(e1, w1.w, bb.w));
        x[j] = xv;
        Sx += xv.x + xv.y + xv.z + xv.w;
        xx += xv.x*xv.x + xv.y*xv.y + xv.z*xv.z + xv.w*xv.w;
        g[j]  = GG[c];
        be[j] = BE[c];
    }
    #pragma unroll
    for (int off = 16; off > 0; off >>= 1) {
        Sx += __shfl_xor_sync(0xffffffffu, Sx, off);
        xx += __shfl_xor_sync(0xffffffffu, xx, off);
    }

    const float invD = 1.0f / (float)D_DIM;
    const size_t rowBase = ((size_t)b * L + l0) * D_DIM;

    // ---- stream RPW rows, one row per warp-iteration ----
    #pragma unroll 2
    for (int r = 0; r < RPW; ++r) {
        if (l0 + r >= L) break;
        const float4* prow = reinterpret_cast<const float4*>(pooler + rowBase + (size_t)r * D_DIM);
        float4*       orow = reinterpret_cast<float4*>(out + rowBase + (size_t)r * D_DIM);

        float4 p[F4_LANE];
        #pragma unroll
        for (int j = 0; j < F4_LANE; ++j)
            p[j] = prow[lane + 32 * j];

        float pp = 0.f, px = 0.f, Sp = 0.f;
        #pragma unroll
        for (int j = 0; j < F4_LANE; ++j) {
            pp = fmaf(p[j].x, p[j].x, fmaf(p[j].y, p[j].y, fmaf(p[j].z, p[j].z, fmaf(p[j].w, p[j].w, pp))));
            px = fmaf(p[j].x, x[j].x, fmaf(p[j].y, x[j].y, fmaf(p[j].z, x[j].z, fmaf(p[j].w, x[j].w, px))));
            Sp += p[j].x + p[j].y + p[j].z + p[j].w;
        }
        #pragma unroll
        for (int off = 16; off > 0; off >>= 1) {
            pp += __shfl_xor_sync(0xffffffffu, pp, off);
            px += __shfl_xor_sync(0xffffffffu, px, off);
            Sp += __shfl_xor_sync(0xffffffffu, Sp, off);
        }

        // 2x2 safe softmax; rows [pp,px] and [px,xx]
        float m0  = fmaxf(pp, px);
        float e00 = __expf(pp - m0), e01 = __expf(px - m0);
        float a00 = e00 / (e00 + e01), a01 = 1.0f - a00;
        float m1  = fmaxf(px, xx);
        float e10 = __expf(px - m1), e11 = __expf(xx - m1);
        float a10 = e10 / (e10 + e11), a11 = 1.0f - a10;

        float wp = a00 + a10;
        float wx = a01 + a11;

        // analytic LN stats of summed = wp*p + wx*x
        float mean = (wp * Sp + wx * Sx) * invD;
        float ss2  = wp*wp*pp + 2.0f*wp*wx*px + wx*wx*xx;
        float var  = ss2 * invD - mean * mean;
        float inv  = rsqrtf(var + LN_EPS);
        float cwp  = wp * inv;            // coefficient on p
        float cwx  = wx * inv;            // coefficient on x
        float cm   = mean * inv;          // subtracted (pre-gamma)

        #pragma unroll
        for (int j = 0; j < F4_LANE; ++j) {
            float4 o;
            o.x = fmaf(fmaf(cwp, p[j].x, fmaf(cwx, x[j].x, -cm)), g[j].x, be[j].x);
            o.y = fmaf(fmaf(cwp, p[j].y, fmaf(cwx, x[j].y, -cm)), g[j].y, be[j].y);
            o.z = fmaf(fmaf(cwp, p[j].z, fmaf(cwx, x[j].z, -cm)), g[j].z, be[j].z);
            o.w = fmaf(fmaf(cwp, p[j].w, fmaf(cwx, x[j].w, -cm)), g[j].w, be[j].w);
            orow[lane + 32 * j] = o;
        }
    }
}

extern "C" void kernel_launch(void* const* d_in, const int* in_sizes, int n_in,
                              void* d_out, int out_size)
{
    const int*   ids    = (const int*)  d_in[0];
    const float* pooler = (const float*)d_in[1];
    const float* emb    = (const float*)d_in[2];
    const float* Wd     = (const float*)d_in[3];
    const float* bd     = (const float*)d_in[4];
    const float* gamma  = (const float*)d_in[5];
    const float* beta   = (const float*)d_in[6];
    float* out = (float*)d_out;

    const int B = in_sizes[0];                      // ids is (B,1)
    const int L = in_sizes[1] / (B * D_DIM);        // pooler is (B,L,D)

    dim3 grid((L + WARPS * RPW - 1) / (WARPS * RPW), B);
    hier_attn_ln_kernel<<<grid, NTHR>>>(ids, pooler, emb, Wd, bd, gamma, beta, out, L);
}